// round 4
// baseline (speedup 1.0000x reference)
#include <cuda_runtime.h>
#include <cuda_bf16.h>

// ---------------------------------------------------------------------------
// GCN forward: h1 = relu(conv(x,W1,b1)); h2 = conv(h1,W2,b2);
// pooled = segment_mean(h2, batch); out = log_softmax(pooled@Wl + bl)
// conv(x,W,b) = dinv ⊙ (Adj_csr · (dinv ⊙ (x@W))) + b   (Adj incl self loops)
// Launch order puts the first GEMM at launch #6 so ncu (-s 5 -c 1) captures it.
// ---------------------------------------------------------------------------

#define MAXN 100000
#define MAXE 640000
#define MAXCSR (MAXN + MAXE)
#define NGRAPH 64
#define HDIM 128

__device__ __align__(16) float d_bufA[MAXN * HDIM];
__device__ __align__(16) float d_bufB[MAXN * HDIM];
__device__ __align__(16) float d_pool[NGRAPH * HDIM];
__device__ int   d_cnt[MAXN];
__device__ int   d_incl[MAXN];
__device__ int   d_bsum[128];
__device__ int   d_rowptr[MAXN + 1];
__device__ int   d_fill[MAXN];
__device__ int   d_csr[MAXCSR];
__device__ float d_dinv[MAXN];
__device__ int   d_is64;

__device__ __forceinline__ int loadIdx(const void* p, int i) {
    return d_is64 ? (int)((const long long*)p)[i] : ((const int*)p)[i];
}

// ---------------- setup: dtype detect + init cnt/fill + zero pool ----------

__global__ void k_setup(const unsigned int* __restrict__ eiw, int N) {
    int i = blockIdx.x * blockDim.x + threadIdx.x;
    if (i < N) { d_cnt[i] = 1; d_fill[i] = 0; }          // cnt=1: self loop
    if (i < NGRAPH * HDIM) d_pool[i] = 0.f;
    if (blockIdx.x == 0) {
        // int64 (<2^31) => all odd 32-bit words zero; int32 => nonzero sum
        __shared__ unsigned long long ssum;
        if (threadIdx.x == 0) ssum = 0;
        __syncthreads();
        unsigned long long local = 0;
        for (int j = 1 + 2 * threadIdx.x; j < 4096; j += 2 * blockDim.x)
            local += eiw[j];
        atomicAdd(&ssum, local);
        __syncthreads();
        if (threadIdx.x == 0) d_is64 = (ssum == 0ULL) ? 1 : 0;
    }
}

// ---------------- degree count ----------------

__global__ void k_count(const void* __restrict__ ei, int E) {
    int e = blockIdx.x * blockDim.x + threadIdx.x;
    if (e < E) atomicAdd(&d_cnt[loadIdx(ei, E + e)], 1);   // dst row
}

// ---------------- block-level inclusive scan of degrees ----------------

__global__ void k_scan1(int N) {
    __shared__ int s[1024];
    int i = blockIdx.x * 1024 + threadIdx.x;
    int v = (i < N) ? d_cnt[i] : 0;
    if (i < N) d_dinv[i] = rsqrtf((float)v);
    s[threadIdx.x] = v;
    __syncthreads();
    for (int off = 1; off < 1024; off <<= 1) {
        int t = (threadIdx.x >= off) ? s[threadIdx.x - off] : 0;
        __syncthreads();
        s[threadIdx.x] += t;
        __syncthreads();
    }
    if (i < N) d_incl[i] = s[threadIdx.x];
    if (threadIdx.x == 1023) d_bsum[blockIdx.x] = s[1023];
}

// rowptr[i] = incl[i] - cnt[i] + prefix(bsum); rowptr[N] = total
__global__ void k_scan3b(int N, int nb) {
    int i = blockIdx.x * blockDim.x + threadIdx.x;
    if (i == 0) {
        int run = 0;
        for (int b = 0; b < nb; b++) run += d_bsum[b];
        d_rowptr[N] = run;
    }
    if (i < N) {
        int blk = i >> 10, base = 0;
        for (int b = 0; b < blk; b++) base += d_bsum[b];
        d_rowptr[i] = d_incl[i] - d_cnt[i] + base;
    }
}

__global__ void k_csrfill(const void* __restrict__ ei, int E, int N) {
    int id = blockIdx.x * blockDim.x + threadIdx.x;
    if (id >= E + N) return;
    int s, dn;
    if (id < E) { s = loadIdx(ei, id); dn = loadIdx(ei, E + id); }
    else        { s = dn = id - E; }                     // self loop
    int pos = d_rowptr[dn] + atomicAdd(&d_fill[dn], 1);
    d_csr[pos] = s;
}

// ---------------- GEMM: out = dinv ⊙ (A @ W), 128x128 tile, 8x8/thread ----
// srcSel: 0 -> Ain (input x), else d_bufB. Writes d_bufA.

__global__ void __launch_bounds__(256) k_gemm2(const float* __restrict__ Ain,
                                               int srcSel,
                                               const float* __restrict__ W,
                                               int N) {
    const float* A = (srcSel == 0) ? Ain : (const float*)d_bufB;
    float* out = d_bufA;

    extern __shared__ __align__(16) float As[];   // [128][132] transposed As[k][r]
    int tid  = threadIdx.x;
    int row0 = blockIdx.x * 128;

    for (int idx = tid; idx < 128 * 128; idx += 256) {
        int r = idx >> 7, k = idx & 127;
        int row = row0 + r;
        As[k * 132 + r] = (row < N) ? A[(long long)row * 128 + k] : 0.f;
    }
    __syncthreads();

    int tx = tid & 15, ty = tid >> 4;      // cols tx*8..+7, rows ty*8..+7
    float acc[8][8];
#pragma unroll
    for (int i = 0; i < 8; i++)
#pragma unroll
        for (int j = 0; j < 8; j++) acc[i][j] = 0.f;

    const float* Wp = W + tx * 8;
    const float* Ap = As + ty * 8;
#pragma unroll 4
    for (int k = 0; k < 128; k++) {
        float4 a0 = *(const float4*)(Ap + k * 132);
        float4 a1 = *(const float4*)(Ap + k * 132 + 4);
        float4 w0 = __ldg((const float4*)(Wp + k * 128));
        float4 w1 = __ldg((const float4*)(Wp + k * 128 + 4));
        float av[8] = {a0.x, a0.y, a0.z, a0.w, a1.x, a1.y, a1.z, a1.w};
        float wv[8] = {w0.x, w0.y, w0.z, w0.w, w1.x, w1.y, w1.z, w1.w};
#pragma unroll
        for (int i = 0; i < 8; i++)
#pragma unroll
            for (int j = 0; j < 8; j++) acc[i][j] += av[i] * wv[j];
    }

#pragma unroll
    for (int i = 0; i < 8; i++) {
        int row = row0 + ty * 8 + i;
        if (row < N) {
            float dd = d_dinv[row];
            float4 o0 = make_float4(acc[i][0]*dd, acc[i][1]*dd, acc[i][2]*dd, acc[i][3]*dd);
            float4 o1 = make_float4(acc[i][4]*dd, acc[i][5]*dd, acc[i][6]*dd, acc[i][7]*dd);
            *(float4*)&out[(long long)row * 128 + tx * 8]     = o0;
            *(float4*)&out[(long long)row * 128 + tx * 8 + 4] = o1;
        }
    }
}

// ---------------- Aggregation: warp per node ----------------

template <bool RELU>
__global__ void k_agg(const float* __restrict__ bias, int N) {
    int w    = (blockIdx.x * blockDim.x + threadIdx.x) >> 5;
    int lane = threadIdx.x & 31;
    if (w >= N) return;
    int rs = d_rowptr[w], re = d_rowptr[w + 1];
    const float4* in4 = (const float4*)d_bufA;
    float4 acc = make_float4(0.f, 0.f, 0.f, 0.f);
    for (int e = rs; e < re; e++) {
        int s = d_csr[e];
        float4 v = __ldg(&in4[s * 32 + lane]);
        acc.x += v.x; acc.y += v.y; acc.z += v.z; acc.w += v.w;
    }
    float dd = d_dinv[w];
    float4 b = __ldg(&((const float4*)bias)[lane]);
    float4 o = make_float4(acc.x * dd + b.x, acc.y * dd + b.y,
                           acc.z * dd + b.z, acc.w * dd + b.w);
    if (RELU) {
        o.x = fmaxf(o.x, 0.f); o.y = fmaxf(o.y, 0.f);
        o.z = fmaxf(o.z, 0.f); o.w = fmaxf(o.w, 0.f);
    }
    ((float4*)d_bufB)[w * 32 + lane] = o;
}

// ---------------- Pool: chunked partial sums + atomics (batch sorted) ------

__global__ void k_poolacc(const void* __restrict__ batch, int N) {
    int c = threadIdx.x;                 // 0..127
    int start = blockIdx.x * 1024;
    if (start >= N) return;
    int end = min(start + 1024, N);
    int curg = loadIdx(batch, start);
    float run = 0.f;
    for (int i = start; i < end; i++) {
        int g = loadIdx(batch, i);
        if (g != curg) {
            atomicAdd(&d_pool[curg * 128 + c], run);
            run = 0.f; curg = g;
        }
        run += d_bufB[(long long)i * 128 + c];
    }
    atomicAdd(&d_pool[curg * 128 + c], run);
}

// ---------------- Final: counts + logits + log_softmax ----------------

__global__ void k_final(const float* __restrict__ Wl, const float* __restrict__ bl,
                        const void* __restrict__ batch, int N,
                        float* __restrict__ out) {
    __shared__ float sl[NGRAPH][10];
    __shared__ float sm[NGRAPH];
    __shared__ float ss[NGRAPH];
    __shared__ float scnt[NGRAPH + 1];   // boundary positions -> counts
    int tid = threadIdx.x;               // 640 threads
    // boundaries: lower_bound(batch, g) for g = 0..64
    if (tid <= NGRAPH) {
        int lo = 0, hi = N;
        while (lo < hi) { int mid = (lo + hi) >> 1; if (loadIdx(batch, mid) < tid) lo = mid + 1; else hi = mid; }
        scnt[tid] = (float)lo;
    }
    __syncthreads();
    int g = tid / 10, c = tid % 10;
    if (tid < NGRAPH * 10) {
        float cnt = fmaxf(scnt[g + 1] - scnt[g], 1.0f);
        float dot = 0.f;
        for (int k = 0; k < 128; k++) dot += d_pool[g * 128 + k] * Wl[k * 10 + c];
        sl[g][c] = dot / cnt + bl[c];
    }
    __syncthreads();
    if (tid < NGRAPH) {
        float m = -1e30f;
        for (int j = 0; j < 10; j++) m = fmaxf(m, sl[tid][j]);
        float s = 0.f;
        for (int j = 0; j < 10; j++) s += expf(sl[tid][j] - m);
        sm[tid] = m; ss[tid] = logf(s);
    }
    __syncthreads();
    if (tid < NGRAPH * 10) out[tid] = sl[g][c] - sm[g] - ss[g];
}

// ---------------- Launch ----------------

extern "C" void kernel_launch(void* const* d_in, const int* in_sizes, int n_in,
                              void* d_out, int out_size) {
    (void)n_in; (void)out_size;
    const float* x     = (const float*)d_in[0];
    const void*  ei    = d_in[1];
    const void*  batch = d_in[2];
    const float* W1    = (const float*)d_in[3];
    const float* b1    = (const float*)d_in[4];
    const float* W2    = (const float*)d_in[5];
    const float* b2    = (const float*)d_in[6];
    const float* Wl    = (const float*)d_in[7];
    const float* bl    = (const float*)d_in[8];
    float* out = (float*)d_out;

    int N = in_sizes[0] / HDIM;
    int E = in_sizes[1] / 2;
    int nb = (N + 1023) >> 10;

    static int smemSet = 0;
    const int GEMM_SMEM = 128 * 132 * 4;   // 67584 bytes
    if (!smemSet) {
        cudaFuncSetAttribute(k_gemm2, cudaFuncAttributeMaxDynamicSharedMemorySize, GEMM_SMEM);
        smemSet = 1;
    }

    // 5 setup launches, so the 6th (ncu -s 5 -c 1 capture target) is the GEMM
    k_setup <<<(N + 255) / 256, 256>>>((const unsigned int*)ei, N);        // 1
    k_count <<<(E + 255) / 256, 256>>>(ei, E);                             // 2
    k_scan1 <<<nb, 1024>>>(N);                                             // 3
    k_scan3b<<<(N + 255) / 256, 256>>>(N, nb);                             // 4
    k_csrfill<<<(E + N + 255) / 256, 256>>>(ei, E, N);                     // 5

    // conv1
    k_gemm2<<<(N + 127) / 128, 256, GEMM_SMEM>>>(x, 0, W1, N);             // 6 <- profiled
    k_agg<true><<<((long long)N * 32 + 255) / 256, 256>>>(b1, N);          // 7

    // conv2
    k_gemm2<<<(N + 127) / 128, 256, GEMM_SMEM>>>(nullptr, 2, W2, N);       // 8
    k_agg<false><<<((long long)N * 32 + 255) / 256, 256>>>(b2, N);         // 9

    // pool + classifier
    k_poolacc<<<(N + 1023) / 1024, 128>>>(batch, N);                       // 10
    k_final<<<1, 640>>>(Wl, bl, batch, N, out);                            // 11
}